// round 4
// baseline (speedup 1.0000x reference)
#include <cuda_runtime.h>
#include <cstdint>

typedef unsigned u32;

#define TT  2048
#define CH  256
#define NCH (TT/CH)
#define HID 512
#define NB  32
#define G4  (4*HID)

// ---------------- device scratch (chunked: ~88MB total) ----------------
__device__ __align__(16) float g_xproj[(size_t)CH * G4 * NB];   // [t_loc][g][b] fp32, 64MB
__device__ __align__(16) u32   g_x_pack[(size_t)CH * HID * NB]; // [t_loc][d][b] packed bf16 hi|lo, 16MB
__device__ __align__(16) u32   g_wih_pack[G4 * HID];            // [g][d] 4MB
__device__ __align__(16) u32   g_whh_pack[G4 * HID];            // [g][k] 4MB
__device__ __align__(16) u32   g_hpack[2 * 4 * HID * 8];        // [parity][group][j][b]
__device__ __align__(16) float g_c[NB * HID];                   // cell state between chunks
__device__ u32 g_bar[128];                                      // group barrier counters (stride 32)

// ---------------- helpers ----------------
__device__ __forceinline__ u32 bf16rn(u32 xb){ return (xb + 0x7FFFu + ((xb >> 16) & 1u)) >> 16; }
__device__ __forceinline__ u32 packbf(float x){
    u32 xb = __float_as_uint(x);
    u32 hi = bf16rn(xb);
    float r = x - __uint_as_float(hi << 16);
    u32 lo = bf16rn(__float_as_uint(r));
    return hi | (lo << 16);
}
__device__ __forceinline__ u32 prmt(u32 a, u32 b, u32 s){
    u32 d; asm("prmt.b32 %0,%1,%2,%3;" : "=r"(d) : "r"(a), "r"(b), "r"(s)); return d;
}
__device__ __forceinline__ void mma_bf16(float* c, const u32* a, u32 b0, u32 b1){
    asm volatile("mma.sync.aligned.m16n8k16.row.col.f32.bf16.bf16.f32 "
                 "{%0,%1,%2,%3},{%4,%5,%6,%7},{%8,%9},{%0,%1,%2,%3};"
                 : "+f"(c[0]), "+f"(c[1]), "+f"(c[2]), "+f"(c[3])
                 : "r"(a[0]), "r"(a[1]), "r"(a[2]), "r"(a[3]), "r"(b0), "r"(b1));
}
__device__ __forceinline__ void cp16(u32* dst, const u32* src){
    u32 d = (u32)__cvta_generic_to_shared(dst);
    asm volatile("cp.async.cg.shared.global [%0], [%1], 16;" :: "r"(d), "l"(src));
}
__device__ __forceinline__ void cp_commit(){ asm volatile("cp.async.commit_group;" ::: "memory"); }
__device__ __forceinline__ void bar_arrive(u32* p){
    asm volatile("red.release.gpu.global.add.u32 [%0], %1;" :: "l"(p), "r"(1u) : "memory");
}
__device__ __forceinline__ u32 ld_acq(const u32* p){
    u32 v; asm volatile("ld.acquire.gpu.global.u32 %0, [%1];" : "=r"(v) : "l"(p) : "memory"); return v;
}
__device__ __forceinline__ float sigm(float x){ return 1.f / (1.f + __expf(-x)); }

// ---------------- kernel 1: reset barriers ----------------
__global__ void k_init(){
    if (threadIdx.x < 4) g_bar[threadIdx.x * 32] = 0;
}

// ---------------- kernel 2: pack weights to bf16 hi|lo ----------------
__global__ void k_packw(const float* __restrict__ wih, const float* __restrict__ whh){
    int id = blockIdx.x * 256 + threadIdx.x;            // 262144 float4s per matrix
    float4 a = ((const float4*)wih)[id];
    uint4 o; o.x = packbf(a.x); o.y = packbf(a.y); o.z = packbf(a.z); o.w = packbf(a.w);
    ((uint4*)g_wih_pack)[id] = o;
    float4 b = ((const float4*)whh)[id];
    uint4 p; p.x = packbf(b.x); p.y = packbf(b.y); p.z = packbf(b.z); p.w = packbf(b.w);
    ((uint4*)g_whh_pack)[id] = p;
}

// ---------------- kernel 3: transpose + pack input chunk -> [t_loc][d][b] ----------------
__global__ void k_packx(const float* __restrict__ input, int tbase){
    __shared__ u32 tile[32 * 129];
    int tl = blockIdx.y, d0 = blockIdx.x * 128, tid = threadIdx.x;
    int t = tbase + tl;
    #pragma unroll
    for (int i = 0; i < 4; i++){
        int id = tid + i * 256;                          // 1024 float4s: [b][q]
        int b = id >> 5, q = id & 31;
        float4 v = *(const float4*)(input + ((size_t)b * TT + t) * HID + d0 + q * 4);
        u32* tp = &tile[b * 129 + q * 4];
        tp[0] = packbf(v.x); tp[1] = packbf(v.y); tp[2] = packbf(v.z); tp[3] = packbf(v.w);
    }
    __syncthreads();
    #pragma unroll
    for (int i = 0; i < 16; i++){
        int id = tid + i * 256;                          // 4096: [r][b]
        int r = id >> 5, b = id & 31;
        g_x_pack[((size_t)tl * HID + d0 + r) * NB + b] = tile[b * 129 + r];
    }
}

// ---------------- kernel 4: xproj GEMM chunk (bf16x3) ----------------
#define SW 40
#define SX 68
#define BUFU (128*SW + 32*SX)   // 7296 u32 per buffer

__device__ __forceinline__ void stage1(u32* smbuf, int tid, int g0, int t0, int kc){
    u32* Wd = smbuf; u32* Xd = smbuf + 128 * SW;
    const int k0 = kc * 32;
    #pragma unroll
    for (int i = 0; i < 4; i++){
        int id = tid + i * 256; int row = id >> 3, c = id & 7;
        cp16(Wd + row * SW + c * 4, g_wih_pack + (g0 + row) * HID + k0 + c * 4);
    }
    #pragma unroll
    for (int i = 0; i < 2; i++){
        int id = tid + i * 256; int k = id >> 4, c = id & 15;
        cp16(Xd + k * SX + c * 4,
             g_x_pack + ((size_t)(t0 + (c >> 3)) * HID + k0 + k) * NB + (c & 7) * 4);
    }
    cp_commit();
}

__global__ void __launch_bounds__(256) k_gemm1(const float* __restrict__ bih,
                                               const float* __restrict__ bhh){
    extern __shared__ u32 sm[];
    __shared__ float bias[128];
    const int tid = threadIdx.x, lane = tid & 31, warp = tid >> 5;
    const int gid = lane >> 2, tig = lane & 3;
    const int m = warp;
    const int g0 = blockIdx.x * 128, t0 = blockIdx.y * 2;   // t0 is chunk-local
    if (tid < 128) bias[tid] = bih[g0 + tid] + bhh[g0 + tid];

    float acc[8][4];
    #pragma unroll
    for (int n = 0; n < 8; n++){ acc[n][0]=0.f; acc[n][1]=0.f; acc[n][2]=0.f; acc[n][3]=0.f; }

    stage1(sm, tid, g0, t0, 0);
    for (int kc = 0; kc < 16; kc++){
        if (kc < 15){
            stage1(sm + ((kc + 1) & 1) * BUFU, tid, g0, t0, kc + 1);
            asm volatile("cp.async.wait_group 1;" ::: "memory");
        } else {
            asm volatile("cp.async.wait_group 0;" ::: "memory");
        }
        __syncthreads();
        const u32* W = sm + (kc & 1) * BUFU;
        const u32* X = W + 128 * SW;
        #pragma unroll
        for (int kt = 0; kt < 2; kt++){
            const int kb = kt * 16;
            u32 ahi[4], alo[4];
            #pragma unroll
            for (int p = 0; p < 4; p++){
                int row = m * 16 + gid + ((p & 1) ? 8 : 0);
                int col = kb + 2 * tig + ((p >= 2) ? 8 : 0);
                uint2 v = *reinterpret_cast<const uint2*>(W + row * SW + col);
                ahi[p] = prmt(v.x, v.y, 0x5410u);
                alo[p] = prmt(v.x, v.y, 0x7632u);
            }
            #pragma unroll
            for (int nt = 0; nt < 8; nt++){
                int n0 = nt * 8 + gid;
                u32 v0 = X[(kb + 2*tig    ) * SX + n0];
                u32 v1 = X[(kb + 2*tig + 1) * SX + n0];
                u32 v2 = X[(kb + 2*tig + 8) * SX + n0];
                u32 v3 = X[(kb + 2*tig + 9) * SX + n0];
                u32 bh0 = prmt(v0, v1, 0x5410u), bh1 = prmt(v2, v3, 0x5410u);
                u32 bl0 = prmt(v0, v1, 0x7632u), bl1 = prmt(v2, v3, 0x7632u);
                mma_bf16(acc[nt], ahi, bh0, bh1);
                mma_bf16(acc[nt], ahi, bl0, bl1);
                mma_bf16(acc[nt], alo, bh0, bh1);
            }
        }
        __syncthreads();
    }
    float bz = bias[m * 16 + gid], bo = bias[m * 16 + gid + 8];
    #pragma unroll
    for (int nt = 0; nt < 8; nt++){
        int n0 = nt * 8 + 2 * tig;
        int t = t0 + (n0 >> 5), b = n0 & 31;
        int gr = g0 + m * 16 + gid;
        size_t o = ((size_t)t * G4 + gr) * NB + b;
        *(float2*)(g_xproj + o)          = make_float2(acc[nt][0] + bz, acc[nt][1] + bz);
        *(float2*)(g_xproj + o + 8 * NB) = make_float2(acc[nt][2] + bo, acc[nt][3] + bo);
    }
}

// ---------------- kernel 5: persistent recurrence over one chunk ----------------
__global__ void __launch_bounds__(256, 1) k_rec(const float* __restrict__ h0,
                                                const float* __restrict__ c0,
                                                float* __restrict__ out, int s0){
    __shared__ u32   Hs[HID * 12];     // stride-12: conflict-free b-frag LDS
    __shared__ float Gt[512];          // [m][u16][b8]
    __shared__ float Red[512];         // [m][lane][4]
    __shared__ float Cs[128];          // [u][b] fp32 cell state

    const int tid = threadIdx.x, lane = tid & 31, warp = tid >> 5;
    const int gid = lane >> 2, tig = lane & 3;
    const int m = warp >> 1, kh = warp & 1;
    const int group = blockIdx.x >> 5, sub = blockIdx.x & 31;
    const int j0 = sub * 16, b0g = group * 8;

    // preload W_hh A-fragments (hi/lo) into registers: 16 ktiles x 4 regs x 2
    u32 ahi[16][4], alo[16][4];
    {
        const int arow = m * HID + j0 + gid;
        #pragma unroll
        for (int kt = 0; kt < 16; kt++){
            int kb = kh * 256 + kt * 16;
            #pragma unroll
            for (int p = 0; p < 4; p++){
                int row = arow + ((p & 1) ? 8 : 0);
                int col = kb + 2 * tig + ((p >= 2) ? 8 : 0);
                uint2 v = *reinterpret_cast<const uint2*>(g_whh_pack + row * HID + col);
                ahi[kt][p] = prmt(v.x, v.y, 0x5410u);
                alo[kt][p] = prmt(v.x, v.y, 0x7632u);
            }
        }
    }

    // prologue
    if (tid < 128){
        int u = tid >> 3, b = tid & 7;
        if (s0 == 0){
            float h = h0[(size_t)(b0g + b) * HID + j0 + u];
            g_hpack[(0 * 4 + group) * (HID * 8) + (j0 + u) * 8 + b] = packbf(h);
            Cs[tid] = c0[(size_t)(b0g + b) * HID + j0 + u];
        } else {
            Cs[tid] = g_c[(size_t)(b0g + b) * HID + j0 + u];
        }
    }
    __syncthreads();
    if (tid == 0 && s0 == 0) bar_arrive(&g_bar[group * 32]);

    const size_t xrow = (size_t)(m * HID + j0 + gid) * NB + b0g + 2 * tig;

    for (int sl = 0; sl < CH; sl++){
        const int s = s0 + sl;                 // global step
        // wait: h_s ready (32*(s+1) arrivals so far)
        if (tid == 0){
            u32 target = 32u * (u32)(s + 1);
            long guard = 0;
            while (ld_acq(&g_bar[group * 32]) < target && guard < (1L << 33)){
                __nanosleep(32); guard++;
            }
        }
        __syncthreads();

        // stage full group h (512 units x 8 batches, packed) into SMEM
        {
            const u32* hp = g_hpack + ((s & 1) * 4 + group) * (HID * 8);
            #pragma unroll
            for (int i = 0; i < 4; i++){
                int id = tid + i * 256; int k = id >> 1, c = id & 1;
                cp16(Hs + k * 12 + c * 4, hp + k * 8 + c * 4);
            }
            cp_commit();
        }
        // prefetch xproj for this step (kh==0 warps), overlaps cp.async
        float2 xa = make_float2(0.f, 0.f), xb = make_float2(0.f, 0.f);
        if (kh == 0){
            const float* xp = g_xproj + (size_t)sl * (G4 * NB) + xrow;
            xa = *(const float2*)xp;
            xb = *(const float2*)(xp + 8 * NB);
        }
        asm volatile("cp.async.wait_group 0;" ::: "memory");
        __syncthreads();

        // MMA over this warp's K half (bf16 hi/lo, 3 products)
        float acc[4] = {0.f, 0.f, 0.f, 0.f};
        #pragma unroll
        for (int kt = 0; kt < 16; kt++){
            int kb = kh * 256 + kt * 16;
            u32 v0 = Hs[(kb + 2*tig    ) * 12 + gid];
            u32 v1 = Hs[(kb + 2*tig + 1) * 12 + gid];
            u32 v2 = Hs[(kb + 2*tig + 8) * 12 + gid];
            u32 v3 = Hs[(kb + 2*tig + 9) * 12 + gid];
            u32 bh0 = prmt(v0, v1, 0x5410u), bh1 = prmt(v2, v3, 0x5410u);
            u32 bl0 = prmt(v0, v1, 0x7632u), bl1 = prmt(v2, v3, 0x7632u);
            mma_bf16(acc, ahi[kt], bh0, bh1);
            mma_bf16(acc, ahi[kt], bl0, bl1);
            mma_bf16(acc, alo[kt], bh0, bh1);
        }

        // cross-warp K reduction
        if (kh == 1){
            float* rp = &Red[(m * 32 + lane) * 4];
            rp[0] = acc[0]; rp[1] = acc[1]; rp[2] = acc[2]; rp[3] = acc[3];
        }
        __syncthreads();
        if (kh == 0){
            const float* rp = &Red[(m * 32 + lane) * 4];
            float* gp = &Gt[(m * 16 + gid) * 8 + 2 * tig];
            gp[0]  = acc[0] + rp[0] + xa.x;
            gp[1]  = acc[1] + rp[1] + xa.y;
            gp[64] = acc[2] + rp[2] + xb.x;
            gp[65] = acc[3] + rp[3] + xb.y;
        }
        __syncthreads();

        // activations + state update (128 threads = 16 units x 8 batches)
        if (tid < 128){
            int u = tid >> 3, b = tid & 7;
            float gi = sigm (Gt[        u * 8 + b]);
            float gf = sigm (Gt[128 +   u * 8 + b]);
            float gg = tanhf(Gt[256 +   u * 8 + b]);
            float go = sigm (Gt[384 +   u * 8 + b]);
            float c  = gf * Cs[tid] + gi * gg;
            Cs[tid]  = c;
            float h  = go * tanhf(c);
            if (s == TT - 1){
                out[(size_t)(b0g + b) * HID + j0 + u]                          = h;
                out[(size_t)NB * HID + (size_t)(b0g + b) * HID + j0 + u]       = c;
            } else {
                g_hpack[(((s + 1) & 1) * 4 + group) * (HID * 8) + (j0 + u) * 8 + b] = packbf(h);
            }
        }
        __syncthreads();
        if (tid == 0 && s < TT - 1) bar_arrive(&g_bar[group * 32]);
    }

    // persist cell state for next chunk
    if (s0 + CH < TT && tid < 128){
        int u = tid >> 3, b = tid & 7;
        g_c[(size_t)(b0g + b) * HID + j0 + u] = Cs[tid];
    }
}

// ---------------- launcher ----------------
extern "C" void kernel_launch(void* const* d_in, const int* in_sizes, int n_in,
                              void* d_out, int out_size){
    const float* input = (const float*)d_in[0];
    const float* h0    = (const float*)d_in[1];
    const float* c0    = (const float*)d_in[2];
    const float* W_ih  = (const float*)d_in[3];
    const float* W_hh  = (const float*)d_in[4];
    const float* b_ih  = (const float*)d_in[5];
    const float* b_hh  = (const float*)d_in[6];
    float* out = (float*)d_out;

    static bool attr_set = false;
    if (!attr_set){
        cudaFuncSetAttribute(k_gemm1, cudaFuncAttributeMaxDynamicSharedMemorySize, 2 * BUFU * 4);
        attr_set = true;
    }

    k_init<<<1, 32>>>();
    k_packw<<<1024, 256>>>(W_ih, W_hh);
    for (int c = 0; c < NCH; c++){
        k_packx<<<dim3(4, CH), 256>>>(input, c * CH);
        k_gemm1<<<dim3(16, CH / 2), 256, 2 * BUFU * 4>>>(b_ih, b_hh);
        k_rec<<<128, 256>>>(h0, c0, out, c * CH);
    }
}

// round 5
// speedup vs baseline: 1.2403x; 1.2403x over previous
#include <cuda_runtime.h>
#include <cstdint>

typedef unsigned u32;
typedef unsigned short u16;

#define TT  2048
#define CH  256
#define NCH (TT/CH)
#define HID 512
#define NB  32
#define G4  (4*HID)
#define HK  (HID/2)   // 256 (k-pair index space)

// ---------------- device scratch (~90MB) ----------------
__device__ __align__(16) float g_xproj[(size_t)CH * G4 * NB];    // [t_loc][g][b] fp32, 64MB
__device__ __align__(16) u32   g_xhi[(size_t)CH * HK * NB];      // hi plane [t][d2][b], 8MB
__device__ __align__(16) u32   g_xlo[(size_t)CH * HK * NB];      // lo plane, 8MB
__device__ __align__(16) u32   g_wih_hi[G4 * HK];                // [g][d2] 2MB
__device__ __align__(16) u32   g_wih_lo[G4 * HK];
__device__ __align__(16) u32   g_whh_hi[G4 * HK];
__device__ __align__(16) u32   g_whh_lo[G4 * HK];
__device__ __align__(16) u32   g_hhi[2 * 4 * HK * 8];            // [par][grp][j2][b]
__device__ __align__(16) u32   g_hlo[2 * 4 * HK * 8];
__device__ __align__(16) float g_c[NB * HID];                    // cell state between chunks
__device__ u32 g_bar[128];                                       // [grp*32 + half*8]

// ---------------- helpers ----------------
__device__ __forceinline__ u32 bf16rn(u32 xb){ return (xb + 0x7FFFu + ((xb >> 16) & 1u)) >> 16; }
__device__ __forceinline__ void splitbf(float x, u32& hi, u32& lo){
    u32 xb = __float_as_uint(x);
    hi = bf16rn(xb);
    float r = x - __uint_as_float(hi << 16);
    lo = bf16rn(__float_as_uint(r));
}
__device__ __forceinline__ u32 packbf(float x){ u32 h, l; splitbf(x, h, l); return h | (l << 16); }
__device__ __forceinline__ u32 prmt(u32 a, u32 b, u32 s){
    u32 d; asm("prmt.b32 %0,%1,%2,%3;" : "=r"(d) : "r"(a), "r"(b), "r"(s)); return d;
}
__device__ __forceinline__ void mma_bf16(float* c, const u32* a, u32 b0, u32 b1){
    asm volatile("mma.sync.aligned.m16n8k16.row.col.f32.bf16.bf16.f32 "
                 "{%0,%1,%2,%3},{%4,%5,%6,%7},{%8,%9},{%0,%1,%2,%3};"
                 : "+f"(c[0]), "+f"(c[1]), "+f"(c[2]), "+f"(c[3])
                 : "r"(a[0]), "r"(a[1]), "r"(a[2]), "r"(a[3]), "r"(b0), "r"(b1));
}
__device__ __forceinline__ void cp16(u32* dst, const u32* src){
    u32 d = (u32)__cvta_generic_to_shared(dst);
    asm volatile("cp.async.cg.shared.global [%0], [%1], 16;" :: "r"(d), "l"(src));
}
__device__ __forceinline__ void cp_commit(){ asm volatile("cp.async.commit_group;" ::: "memory"); }
__device__ __forceinline__ void bar_arrive(u32* p){
    asm volatile("red.release.gpu.global.add.u32 [%0], %1;" :: "l"(p), "r"(1u) : "memory");
}
__device__ __forceinline__ u32 ld_acq(const u32* p){
    u32 v; asm volatile("ld.acquire.gpu.global.u32 %0, [%1];" : "=r"(v) : "l"(p) : "memory"); return v;
}
__device__ __forceinline__ void barn(int id){ asm volatile("bar.sync %0, 128;" :: "r"(id) : "memory"); }
__device__ __forceinline__ float sigm(float x){ return 1.f / (1.f + __expf(-x)); }

// ---------------- kernel 1: reset barriers ----------------
__global__ void k_init(){
    if (threadIdx.x < 128) g_bar[threadIdx.x] = 0;
}

// ---------------- kernel 2: pack weights into hi/lo planes ----------------
__global__ void k_packw(const float* __restrict__ wih, const float* __restrict__ whh){
    int id = blockIdx.x * 256 + threadIdx.x;            // 262144: g = id>>7, q = id&127 (d0=q*4)
    {
        float4 a = ((const float4*)wih)[id];
        u32 p0 = packbf(a.x), p1 = packbf(a.y), p2 = packbf(a.z), p3 = packbf(a.w);
        uint2 hi = make_uint2(prmt(p0, p1, 0x5410u), prmt(p2, p3, 0x5410u));
        uint2 lo = make_uint2(prmt(p0, p1, 0x7632u), prmt(p2, p3, 0x7632u));
        ((uint2*)g_wih_hi)[id] = hi;
        ((uint2*)g_wih_lo)[id] = lo;
    }
    {
        float4 a = ((const float4*)whh)[id];
        u32 p0 = packbf(a.x), p1 = packbf(a.y), p2 = packbf(a.z), p3 = packbf(a.w);
        uint2 hi = make_uint2(prmt(p0, p1, 0x5410u), prmt(p2, p3, 0x5410u));
        uint2 lo = make_uint2(prmt(p0, p1, 0x7632u), prmt(p2, p3, 0x7632u));
        ((uint2*)g_whh_hi)[id] = hi;
        ((uint2*)g_whh_lo)[id] = lo;
    }
}

// ---------------- kernel 3: transpose + pack input chunk into hi/lo planes ----------------
__global__ void k_packx(const float* __restrict__ input, int tbase){
    __shared__ u32 tile[32 * 129];
    int tl = blockIdx.y, d0 = blockIdx.x * 128, tid = threadIdx.x;
    int t = tbase + tl;
    #pragma unroll
    for (int i = 0; i < 4; i++){
        int id = tid + i * 256;                          // 1024 float4s: [b][q]
        int b = id >> 5, q = id & 31;
        float4 v = *(const float4*)(input + ((size_t)b * TT + t) * HID + d0 + q * 4);
        u32* tp = &tile[b * 129 + q * 4];
        tp[0] = packbf(v.x); tp[1] = packbf(v.y); tp[2] = packbf(v.z); tp[3] = packbf(v.w);
    }
    __syncthreads();
    #pragma unroll
    for (int i = 0; i < 8; i++){
        int id = tid + i * 256;                          // 2048: [r2][b]
        int r2 = id >> 5, b = id & 31;
        u32 p0 = tile[b * 129 + 2 * r2], p1 = tile[b * 129 + 2 * r2 + 1];
        size_t o = ((size_t)tl * HK + (d0 >> 1) + r2) * NB + b;
        g_xhi[o] = prmt(p0, p1, 0x5410u);
        g_xlo[o] = prmt(p0, p1, 0x7632u);
    }
}

// ---------------- kernel 4: xproj GEMM chunk (bf16x3, pre-split planes) ----------------
#define SWH 20
#define SX  72
#define BUFU (2*128*SWH + 2*16*SX)   // 7424 u32 per buffer

__device__ __forceinline__ void stage1(u32* buf, int tid, int g0, int t0, int kc){
    u32* Whi = buf;
    u32* Wlo = buf + 128 * SWH;
    u32* Xhi = buf + 2 * 128 * SWH;
    u32* Xlo = Xhi + 16 * SX;
    const int k2_0 = kc * 16;
    #pragma unroll
    for (int i = 0; i < 4; i++){
        int id = i * 256 + tid;                 // [0,1024)
        int plane = id >> 9, rem = id & 511;
        int row = rem >> 2, c = rem & 3;
        u32* dst = (plane ? Wlo : Whi) + row * SWH + c * 4;
        const u32* src = (plane ? g_wih_lo : g_wih_hi) + (size_t)(g0 + row) * HK + k2_0 + c * 4;
        cp16(dst, src);
    }
    #pragma unroll
    for (int i = 0; i < 2; i++){
        int id = i * 256 + tid;                 // [0,512)
        int plane = id >> 8, rem = id & 255;
        int k2 = rem >> 4, c = rem & 15;
        u32* dst = (plane ? Xlo : Xhi) + k2 * SX + c * 4;
        const u32* src = (plane ? g_xlo : g_xhi)
            + ((size_t)(t0 + (c >> 3)) * HK + k2_0 + k2) * NB + (c & 7) * 4;
        cp16(dst, src);
    }
    cp_commit();
}

__global__ void __launch_bounds__(256) k_gemm1(const float* __restrict__ bih,
                                               const float* __restrict__ bhh){
    extern __shared__ u32 sm[];
    __shared__ float bias[128];
    const int tid = threadIdx.x, lane = tid & 31, warp = tid >> 5;
    const int gid = lane >> 2, tig = lane & 3;
    const int m = warp;
    const int g0 = blockIdx.x * 128, t0 = blockIdx.y * 2;   // chunk-local t
    if (tid < 128) bias[tid] = bih[g0 + tid] + bhh[g0 + tid];

    float acc[8][4];
    #pragma unroll
    for (int n = 0; n < 8; n++){ acc[n][0]=0.f; acc[n][1]=0.f; acc[n][2]=0.f; acc[n][3]=0.f; }

    stage1(sm, tid, g0, t0, 0);
    for (int kc = 0; kc < 16; kc++){
        if (kc < 15){
            stage1(sm + ((kc + 1) & 1) * BUFU, tid, g0, t0, kc + 1);
            asm volatile("cp.async.wait_group 1;" ::: "memory");
        } else {
            asm volatile("cp.async.wait_group 0;" ::: "memory");
        }
        __syncthreads();
        const u32* Whi = sm + (kc & 1) * BUFU;
        const u32* Wlo = Whi + 128 * SWH;
        const u32* Xhi = Whi + 2 * 128 * SWH;
        const u32* Xlo = Xhi + 16 * SX;
        #pragma unroll
        for (int kt = 0; kt < 2; kt++){
            const int kb2 = kt * 8;
            u32 ahi[4], alo[4];
            #pragma unroll
            for (int p = 0; p < 4; p++){
                int row  = m * 16 + gid + ((p & 1) ? 8 : 0);
                int col2 = kb2 + tig + ((p >= 2) ? 4 : 0);
                ahi[p] = Whi[row * SWH + col2];
                alo[p] = Wlo[row * SWH + col2];
            }
            #pragma unroll
            for (int nt = 0; nt < 8; nt++){
                int n0 = nt * 8 + gid;
                u32 bh0 = Xhi[(kb2 + tig    ) * SX + n0];
                u32 bh1 = Xhi[(kb2 + tig + 4) * SX + n0];
                u32 bl0 = Xlo[(kb2 + tig    ) * SX + n0];
                u32 bl1 = Xlo[(kb2 + tig + 4) * SX + n0];
                mma_bf16(acc[nt], ahi, bh0, bh1);
                mma_bf16(acc[nt], ahi, bl0, bl1);
                mma_bf16(acc[nt], alo, bh0, bh1);
            }
        }
        __syncthreads();
    }
    float bz = bias[m * 16 + gid], bo = bias[m * 16 + gid + 8];
    #pragma unroll
    for (int nt = 0; nt < 8; nt++){
        int n0 = nt * 8 + 2 * tig;
        int t = t0 + (n0 >> 5), b = n0 & 31;
        int gr = g0 + m * 16 + gid;
        size_t o = ((size_t)t * G4 + gr) * NB + b;
        *(float2*)(g_xproj + o)          = make_float2(acc[nt][0] + bz, acc[nt][1] + bz);
        *(float2*)(g_xproj + o + 8 * NB) = make_float2(acc[nt][2] + bo, acc[nt][3] + bo);
    }
}

// ---------------- kernel 5: persistent recurrence over one chunk ----------------
__global__ void __launch_bounds__(256, 1) k_rec(const float* __restrict__ h0,
                                                const float* __restrict__ c0,
                                                float* __restrict__ out, int s0){
    __shared__ u32   Hshi[HK * 8];     // [j2][b] hi plane, 8KB (stride 8, conflict-free)
    __shared__ u32   Hslo[HK * 8];
    __shared__ float Gt[512];          // [gate][u16][b8]
    __shared__ float Red[512];         // [m][lane][4]
    __shared__ float Cs[128];          // [u][b] fp32 cell state

    const int tid = threadIdx.x, lane = tid & 31, warp = tid >> 5;
    const int gid = lane >> 2, tig = lane & 3;
    const int m = warp >> 1, kh = warp & 1;
    const int gidx = (warp >> 1) * 32 + lane;          // index within kh-group [0,128)
    const int group = blockIdx.x >> 5, sub = blockIdx.x & 31;
    const int j0 = sub * 16, b0g = group * 8;

    // preload W_hh A-fragments (hi/lo planes) into registers
    u32 ahi[16][4], alo[16][4];
    {
        #pragma unroll
        for (int kt = 0; kt < 16; kt++){
            int kb2 = kh * 128 + kt * 8;
            #pragma unroll
            for (int p = 0; p < 4; p++){
                int row  = m * HID + j0 + gid + ((p & 1) ? 8 : 0);
                int col2 = kb2 + tig + ((p >= 2) ? 4 : 0);
                ahi[kt][p] = g_whh_hi[(size_t)row * HK + col2];
                alo[kt][p] = g_whh_lo[(size_t)row * HK + col2];
            }
        }
    }

    // prologue
    if (tid < 128){
        int u = tid >> 3, b = tid & 7, j = j0 + u;
        if (s0 == 0){
            float h = h0[(size_t)(b0g + b) * HID + j];
            u32 hi, lo; splitbf(h, hi, lo);
            size_t idx = (size_t)(0 * 4 + group) * (HK * 8) + (j >> 1) * 8 + b;
            ((u16*)(g_hhi + idx))[j & 1] = (u16)hi;
            ((u16*)(g_hlo + idx))[j & 1] = (u16)lo;
            Cs[tid] = c0[(size_t)(b0g + b) * HID + j];
        } else {
            Cs[tid] = g_c[(size_t)(b0g + b) * HID + j];
        }
    }
    __syncthreads();
    if (tid == 0 && s0 == 0) bar_arrive(&g_bar[group * 32 + ((sub < 16) ? 0 : 8)]);

    const size_t xrow = (size_t)(m * HID + j0 + gid) * NB + b0g + 2 * tig;

    for (int sl = 0; sl < CH; sl++){
        const int s = s0 + sl;                 // global step

        // prefetch xproj (independent of barrier)
        float2 xa = make_float2(0.f, 0.f), xb = make_float2(0.f, 0.f);
        if (kh == 0){
            const float* xp = g_xproj + (size_t)sl * (G4 * NB) + xrow;
            xa = *(const float2*)xp;
            xb = *(const float2*)(xp + 8 * NB);
        }

        // per-half poll: kh half needs units [kh*256, kh*256+256) = subs [kh*16, +16)
        if (lane == 0){
            const u32* bp = &g_bar[group * 32 + kh * 8];
            u32 target = 16u * (u32)(s + 1);
            long guard = 0;
            while (ld_acq(bp) < target && guard < (1L << 31)){ __nanosleep(20); guard++; }
        }
        __syncwarp();

        // stage this kh-half of h (both planes) into SMEM
        {
            const size_t hoff = ((size_t)(s & 1) * 4 + group) * (HK * 8) + (size_t)kh * 1024;
            #pragma unroll
            for (int i = 0; i < 2; i++){
                int id = gidx + i * 128;       // [0,256)
                cp16(Hshi + kh * 1024 + id * 4, g_hhi + hoff + id * 4);
                cp16(Hslo + kh * 1024 + id * 4, g_hlo + hoff + id * 4);
            }
            cp_commit();
        }
        asm volatile("cp.async.wait_group 0;" ::: "memory");
        barn(1 + kh);                          // all 4 warps of this half staged

        // MMA over this warp's K half — 3 independent accumulator chains
        float aH[4] = {0.f,0.f,0.f,0.f}, aM[4] = {0.f,0.f,0.f,0.f}, aL[4] = {0.f,0.f,0.f,0.f};
        #pragma unroll
        for (int kt = 0; kt < 16; kt++){
            int kb2 = kh * 128 + kt * 8;
            u32 bh0 = Hshi[(kb2 + tig    ) * 8 + gid];
            u32 bh1 = Hshi[(kb2 + tig + 4) * 8 + gid];
            u32 bl0 = Hslo[(kb2 + tig    ) * 8 + gid];
            u32 bl1 = Hslo[(kb2 + tig + 4) * 8 + gid];
            mma_bf16(aH, ahi[kt], bh0, bh1);
            mma_bf16(aM, ahi[kt], bl0, bl1);
            mma_bf16(aL, alo[kt], bh0, bh1);
        }
        float acc[4];
        #pragma unroll
        for (int i = 0; i < 4; i++) acc[i] = aH[i] + aM[i] + aL[i];

        // cross-warp K reduction
        if (kh == 1){
            float* rp = &Red[(m * 32 + lane) * 4];
            rp[0] = acc[0]; rp[1] = acc[1]; rp[2] = acc[2]; rp[3] = acc[3];
        }
        __syncthreads();
        if (kh == 0){
            const float* rp = &Red[(m * 32 + lane) * 4];
            float* gp = &Gt[(m * 16 + gid) * 8 + 2 * tig];
            gp[0]  = acc[0] + rp[0] + xa.x;
            gp[1]  = acc[1] + rp[1] + xa.y;
            gp[64] = acc[2] + rp[2] + xb.x;
            gp[65] = acc[3] + rp[3] + xb.y;
        }
        __syncthreads();

        // activations + state update (128 threads = 16 units x 8 batches)
        if (tid < 128){
            int u = tid >> 3, b = tid & 7, j = j0 + u;
            float gi = sigm (Gt[        u * 8 + b]);
            float gf = sigm (Gt[128 +   u * 8 + b]);
            float gg = tanhf(Gt[256 +   u * 8 + b]);
            float go = sigm (Gt[384 +   u * 8 + b]);
            float c  = gf * Cs[tid] + gi * gg;
            Cs[tid]  = c;
            float h  = go * tanhf(c);
            if (s == TT - 1){
                out[(size_t)(b0g + b) * HID + j]                          = h;
                out[(size_t)NB * HID + (size_t)(b0g + b) * HID + j]       = c;
            } else {
                u32 hi, lo; splitbf(h, hi, lo);
                size_t idx = ((size_t)((s + 1) & 1) * 4 + group) * (HK * 8) + (j >> 1) * 8 + b;
                ((u16*)(g_hhi + idx))[j & 1] = (u16)hi;
                ((u16*)(g_hlo + idx))[j & 1] = (u16)lo;
            }
        }
        __syncthreads();
        if (tid == 0 && s < TT - 1) bar_arrive(&g_bar[group * 32 + ((sub < 16) ? 0 : 8)]);
    }

    // persist cell state for next chunk
    if (s0 + CH < TT && tid < 128){
        int u = tid >> 3, b = tid & 7;
        g_c[(size_t)(b0g + b) * HID + j0 + u] = Cs[tid];
    }
}

// ---------------- launcher ----------------
extern "C" void kernel_launch(void* const* d_in, const int* in_sizes, int n_in,
                              void* d_out, int out_size){
    const float* input = (const float*)d_in[0];
    const float* h0    = (const float*)d_in[1];
    const float* c0    = (const float*)d_in[2];
    const float* W_ih  = (const float*)d_in[3];
    const float* W_hh  = (const float*)d_in[4];
    const float* b_ih  = (const float*)d_in[5];
    const float* b_hh  = (const float*)d_in[6];
    float* out = (float*)d_out;

    static bool attr_set = false;
    if (!attr_set){
        cudaFuncSetAttribute(k_gemm1, cudaFuncAttributeMaxDynamicSharedMemorySize, 2 * BUFU * 4);
        attr_set = true;
    }

    k_init<<<1, 128>>>();
    k_packw<<<1024, 256>>>(W_ih, W_hh);
    for (int c = 0; c < NCH; c++){
        k_packx<<<dim3(4, CH), 256>>>(input, c * CH);
        k_gemm1<<<dim3(16, CH / 2), 256, 2 * BUFU * 4>>>(b_ih, b_hh);
        k_rec<<<128, 256>>>(h0, c0, out, c * CH);
    }
}

// round 10
// speedup vs baseline: 1.3285x; 1.0711x over previous
#include <cuda_runtime.h>
#include <cstdint>

typedef unsigned u32;
typedef unsigned short u16;

#define TT  2048
#define CH  128
#define NCH (TT/CH)
#define HID 512
#define NB  32
#define G4  (4*HID)
#define HK  (HID/2)   // 256 (k-pair index space)

#define XPROJ_VOL ((size_t)CH * G4 * NB)
#define XPACK_VOL ((size_t)CH * HK * NB)

// ---------------- device scratch (~91MB, double-buffered for overlap) ----------------
__device__ __align__(16) float g_xproj[2 * XPROJ_VOL];           // [buf][t_loc][g][b] fp32
__device__ __align__(16) u32   g_xhi[2 * XPACK_VOL];             // [buf][t][d2][b]
__device__ __align__(16) u32   g_xlo[2 * XPACK_VOL];
__device__ __align__(16) u32   g_wih_hi[G4 * HK];                // [g][d2]
__device__ __align__(16) u32   g_wih_lo[G4 * HK];
__device__ __align__(16) u32   g_whh_hi[G4 * HK];
__device__ __align__(16) u32   g_whh_lo[G4 * HK];
__device__ __align__(16) u32   g_hhi[2 * 4 * HK * 8];            // [par][grp][j2][b]
__device__ __align__(16) u32   g_hlo[2 * 4 * HK * 8];
__device__ __align__(16) float g_c[NB * HID];                    // cell state between chunks
__device__ u32 g_bar[128];                                       // [grp*32 + half*8]

// ---------------- helpers ----------------
__device__ __forceinline__ u32 bf16rn(u32 xb){ return (xb + 0x7FFFu + ((xb >> 16) & 1u)) >> 16; }
__device__ __forceinline__ void splitbf(float x, u32& hi, u32& lo){
    u32 xb = __float_as_uint(x);
    hi = bf16rn(xb);
    float r = x - __uint_as_float(hi << 16);
    lo = bf16rn(__float_as_uint(r));
}
__device__ __forceinline__ u32 packbf(float x){ u32 h, l; splitbf(x, h, l); return h | (l << 16); }
__device__ __forceinline__ u32 prmt(u32 a, u32 b, u32 s){
    u32 d; asm("prmt.b32 %0,%1,%2,%3;" : "=r"(d) : "r"(a), "r"(b), "r"(s)); return d;
}
__device__ __forceinline__ void mma_bf16(float* c, const u32* a, u32 b0, u32 b1){
    asm volatile("mma.sync.aligned.m16n8k16.row.col.f32.bf16.bf16.f32 "
                 "{%0,%1,%2,%3},{%4,%5,%6,%7},{%8,%9},{%0,%1,%2,%3};"
                 : "+f"(c[0]), "+f"(c[1]), "+f"(c[2]), "+f"(c[3])
                 : "r"(a[0]), "r"(a[1]), "r"(a[2]), "r"(a[3]), "r"(b0), "r"(b1));
}
__device__ __forceinline__ void cp16(u32* dst, const u32* src){
    u32 d = (u32)__cvta_generic_to_shared(dst);
    asm volatile("cp.async.cg.shared.global [%0], [%1], 16;" :: "r"(d), "l"(src));
}
__device__ __forceinline__ void cp_commit(){ asm volatile("cp.async.commit_group;" ::: "memory"); }
__device__ __forceinline__ void bar_arrive(u32* p){
    asm volatile("red.release.gpu.global.add.u32 [%0], %1;" :: "l"(p), "r"(1u) : "memory");
}
__device__ __forceinline__ u32 ld_acq(const u32* p){
    u32 v; asm volatile("ld.acquire.gpu.global.u32 %0, [%1];" : "=r"(v) : "l"(p) : "memory"); return v;
}
__device__ __forceinline__ void barn(int id){ asm volatile("bar.sync %0, 128;" :: "r"(id) : "memory"); }
__device__ __forceinline__ float sigm(float x){ return 1.f / (1.f + __expf(-x)); }

// ---------------- kernel 1: reset barriers ----------------
__global__ void k_init(){
    if (threadIdx.x < 128) g_bar[threadIdx.x] = 0;
}

// ---------------- kernel 2: pack weights into hi/lo planes ----------------
__global__ void k_packw(const float* __restrict__ wih, const float* __restrict__ whh){
    int id = blockIdx.x * 256 + threadIdx.x;            // 262144 float4s per matrix
    {
        float4 a = ((const float4*)wih)[id];
        u32 p0 = packbf(a.x), p1 = packbf(a.y), p2 = packbf(a.z), p3 = packbf(a.w);
        ((uint2*)g_wih_hi)[id] = make_uint2(prmt(p0, p1, 0x5410u), prmt(p2, p3, 0x5410u));
        ((uint2*)g_wih_lo)[id] = make_uint2(prmt(p0, p1, 0x7632u), prmt(p2, p3, 0x7632u));
    }
    {
        float4 a = ((const float4*)whh)[id];
        u32 p0 = packbf(a.x), p1 = packbf(a.y), p2 = packbf(a.z), p3 = packbf(a.w);
        ((uint2*)g_whh_hi)[id] = make_uint2(prmt(p0, p1, 0x5410u), prmt(p2, p3, 0x5410u));
        ((uint2*)g_whh_lo)[id] = make_uint2(prmt(p0, p1, 0x7632u), prmt(p2, p3, 0x7632u));
    }
}

// ---------------- kernel 3: transpose + pack input chunk into hi/lo planes ----------------
__global__ void k_packx(const float* __restrict__ input, int tbase, int buf){
    __shared__ u32 tile[32 * 129];
    int tl = blockIdx.y, d0 = blockIdx.x * 128, tid = threadIdx.x;
    int t = tbase + tl;
    #pragma unroll
    for (int i = 0; i < 4; i++){
        int id = tid + i * 256;                          // 1024 float4s: [b][q]
        int b = id >> 5, q = id & 31;
        float4 v = *(const float4*)(input + ((size_t)b * TT + t) * HID + d0 + q * 4);
        u32* tp = &tile[b * 129 + q * 4];
        tp[0] = packbf(v.x); tp[1] = packbf(v.y); tp[2] = packbf(v.z); tp[3] = packbf(v.w);
    }
    __syncthreads();
    #pragma unroll
    for (int i = 0; i < 8; i++){
        int id = tid + i * 256;                          // 2048: [r2][b]
        int r2 = id >> 5, b = id & 31;
        u32 p0 = tile[b * 129 + 2 * r2], p1 = tile[b * 129 + 2 * r2 + 1];
        size_t o = (size_t)buf * XPACK_VOL + ((size_t)tl * HK + (d0 >> 1) + r2) * NB + b;
        g_xhi[o] = prmt(p0, p1, 0x5410u);
        g_xlo[o] = prmt(p0, p1, 0x7632u);
    }
}

// ---------------- kernel 4: xproj GEMM chunk (bf16x3, pre-split planes) ----------------
#define SWH 20
#define SX  72
#define BUFU (2*128*SWH + 2*16*SX)   // 7424 u32 per buffer

__device__ __forceinline__ void stage1(u32* buf, int tid, int g0, int t0, int kc, size_t xoff){
    u32* Whi = buf;
    u32* Wlo = buf + 128 * SWH;
    u32* Xhi = buf + 2 * 128 * SWH;
    u32* Xlo = Xhi + 16 * SX;
    const int k2_0 = kc * 16;
    #pragma unroll
    for (int i = 0; i < 4; i++){
        int id = i * 256 + tid;                 // [0,1024)
        int plane = id >> 9, rem = id & 511;
        int row = rem >> 2, c = rem & 3;
        u32* dst = (plane ? Wlo : Whi) + row * SWH + c * 4;
        const u32* src = (plane ? g_wih_lo : g_wih_hi) + (size_t)(g0 + row) * HK + k2_0 + c * 4;
        cp16(dst, src);
    }
    #pragma unroll
    for (int i = 0; i < 2; i++){
        int id = i * 256 + tid;                 // [0,512)
        int plane = id >> 8, rem = id & 255;
        int k2 = rem >> 4, c = rem & 15;
        u32* dst = (plane ? Xlo : Xhi) + k2 * SX + c * 4;
        const u32* src = (plane ? g_xlo : g_xhi) + xoff
            + ((size_t)(t0 + (c >> 3)) * HK + k2_0 + k2) * NB + (c & 7) * 4;
        cp16(dst, src);
    }
    cp_commit();
}

__global__ void __launch_bounds__(256) k_gemm1(const float* __restrict__ bih,
                                               const float* __restrict__ bhh, int xbuf){
    extern __shared__ u32 sm[];
    __shared__ float bias[128];
    const int tid = threadIdx.x, lane = tid & 31, warp = tid >> 5;
    const int gid = lane >> 2, tig = lane & 3;
    const int m = warp;
    const int g0 = blockIdx.x * 128, t0 = blockIdx.y * 2;   // chunk-local t
    const size_t xoff = (size_t)xbuf * XPACK_VOL;
    if (tid < 128) bias[tid] = bih[g0 + tid] + bhh[g0 + tid];

    float acc[8][4];
    #pragma unroll
    for (int n = 0; n < 8; n++){ acc[n][0]=0.f; acc[n][1]=0.f; acc[n][2]=0.f; acc[n][3]=0.f; }

    stage1(sm, tid, g0, t0, 0, xoff);
    for (int kc = 0; kc < 16; kc++){
        if (kc < 15){
            stage1(sm + ((kc + 1) & 1) * BUFU, tid, g0, t0, kc + 1, xoff);
            asm volatile("cp.async.wait_group 1;" ::: "memory");
        } else {
            asm volatile("cp.async.wait_group 0;" ::: "memory");
        }
        __syncthreads();
        const u32* Whi = sm + (kc & 1) * BUFU;
        const u32* Wlo = Whi + 128 * SWH;
        const u32* Xhi = Whi + 2 * 128 * SWH;
        const u32* Xlo = Xhi + 16 * SX;
        #pragma unroll
        for (int kt = 0; kt < 2; kt++){
            const int kb2 = kt * 8;
            u32 ahi[4], alo[4];
            #pragma unroll
            for (int p = 0; p < 4; p++){
                int row  = m * 16 + gid + ((p & 1) ? 8 : 0);
                int col2 = kb2 + tig + ((p >= 2) ? 4 : 0);
                ahi[p] = Whi[row * SWH + col2];
                alo[p] = Wlo[row * SWH + col2];
            }
            #pragma unroll
            for (int nt = 0; nt < 8; nt++){
                int n0 = nt * 8 + gid;
                u32 bh0 = Xhi[(kb2 + tig    ) * SX + n0];
                u32 bh1 = Xhi[(kb2 + tig + 4) * SX + n0];
                u32 bl0 = Xlo[(kb2 + tig    ) * SX + n0];
                u32 bl1 = Xlo[(kb2 + tig + 4) * SX + n0];
                mma_bf16(acc[nt], ahi, bh0, bh1);
                mma_bf16(acc[nt], ahi, bl0, bl1);
                mma_bf16(acc[nt], alo, bh0, bh1);
            }
        }
        __syncthreads();
    }
    float bz = bias[m * 16 + gid], bo = bias[m * 16 + gid + 8];
    #pragma unroll
    for (int nt = 0; nt < 8; nt++){
        int n0 = nt * 8 + 2 * tig;
        int t = t0 + (n0 >> 5), b = n0 & 31;
        int gr = g0 + m * 16 + gid;
        size_t o = (size_t)xbuf * XPROJ_VOL + ((size_t)t * G4 + gr) * NB + b;
        *(float2*)(g_xproj + o)          = make_float2(acc[nt][0] + bz, acc[nt][1] + bz);
        *(float2*)(g_xproj + o + 8 * NB) = make_float2(acc[nt][2] + bo, acc[nt][3] + bo);
    }
}

// ---------------- kernel 5: persistent recurrence over one chunk ----------------
__global__ void __launch_bounds__(256, 1) k_rec(const float* __restrict__ h0,
                                                const float* __restrict__ c0,
                                                float* __restrict__ out, int s0, int xbuf){
    __shared__ u32   Hshi[HK * 8];     // [j2][b] hi plane (stride 8, conflict-free)
    __shared__ u32   Hslo[HK * 8];
    __shared__ float Gt[512];          // [gate][u16][b8]
    __shared__ float Red[512];         // [m][lane][4]
    __shared__ float Cs[128];          // [u][b] fp32 cell state

    const int tid = threadIdx.x, lane = tid & 31, warp = tid >> 5;
    const int gid = lane >> 2, tig = lane & 3;
    const int m = warp >> 1, kh = warp & 1;
    const int gidx = (warp >> 1) * 32 + lane;          // index within kh-group [0,128)
    const int group = blockIdx.x >> 5, sub = blockIdx.x & 31;
    const int j0 = sub * 16, b0g = group * 8;

    // preload W_hh A-fragments (hi/lo planes) into registers
    u32 ahi[16][4], alo[16][4];
    {
        #pragma unroll
        for (int kt = 0; kt < 16; kt++){
            int kb2 = kh * 128 + kt * 8;
            #pragma unroll
            for (int p = 0; p < 4; p++){
                int row  = m * HID + j0 + gid + ((p & 1) ? 8 : 0);
                int col2 = kb2 + tig + ((p >= 2) ? 4 : 0);
                ahi[kt][p] = g_whh_hi[(size_t)row * HK + col2];
                alo[kt][p] = g_whh_lo[(size_t)row * HK + col2];
            }
        }
    }

    // prologue
    if (tid < 128){
        int u = tid >> 3, b = tid & 7, j = j0 + u;
        if (s0 == 0){
            float h = h0[(size_t)(b0g + b) * HID + j];
            u32 hi, lo; splitbf(h, hi, lo);
            size_t idx = (size_t)(0 * 4 + group) * (HK * 8) + (j >> 1) * 8 + b;
            ((u16*)(g_hhi + idx))[j & 1] = (u16)hi;
            ((u16*)(g_hlo + idx))[j & 1] = (u16)lo;
            Cs[tid] = c0[(size_t)(b0g + b) * HID + j];
        } else {
            Cs[tid] = g_c[(size_t)(b0g + b) * HID + j];
        }
    }
    __syncthreads();
    if (tid == 0 && s0 == 0) bar_arrive(&g_bar[group * 32 + ((sub < 16) ? 0 : 8)]);

    const size_t xrow = (size_t)(m * HID + j0 + gid) * NB + b0g + 2 * tig;
    const float* xbase = g_xproj + (size_t)xbuf * XPROJ_VOL;

    for (int sl = 0; sl < CH; sl++){
        const int s = s0 + sl;                 // global step

        // prefetch xproj (independent of barrier)
        float2 xa = make_float2(0.f, 0.f), xb = make_float2(0.f, 0.f);
        if (kh == 0){
            const float* xp = xbase + (size_t)sl * (G4 * NB) + xrow;
            xa = *(const float2*)xp;
            xb = *(const float2*)(xp + 8 * NB);
        }

        // per-half poll (tight spin on L2)
        if (lane == 0){
            const u32* bp = &g_bar[group * 32 + kh * 8];
            u32 target = 16u * (u32)(s + 1);
            long guard = 0;
            while (ld_acq(bp) < target && guard < (1L << 26)) guard++;
        }
        __syncwarp();

        // stage this kh-half of h (both planes) into SMEM
        {
            const size_t hoff = ((size_t)(s & 1) * 4 + group) * (HK * 8) + (size_t)kh * 1024;
            #pragma unroll
            for (int i = 0; i < 2; i++){
                int id = gidx + i * 128;       // [0,256)
                cp16(Hshi + kh * 1024 + id * 4, g_hhi + hoff + id * 4);
                cp16(Hslo + kh * 1024 + id * 4, g_hlo + hoff + id * 4);
            }
            cp_commit();
        }
        asm volatile("cp.async.wait_group 0;" ::: "memory");
        barn(1 + kh);                          // all 4 warps of this half staged

        // MMA over this warp's K half — 3 independent accumulator chains
        float aH[4] = {0.f,0.f,0.f,0.f}, aM[4] = {0.f,0.f,0.f,0.f}, aL[4] = {0.f,0.f,0.f,0.f};
        #pragma unroll
        for (int kt = 0; kt < 16; kt++){
            int kb2 = kh * 128 + kt * 8;
            u32 bh0 = Hshi[(kb2 + tig    ) * 8 + gid];
            u32 bh1 = Hshi[(kb2 + tig + 4) * 8 + gid];
            u32 bl0 = Hslo[(kb2 + tig    ) * 8 + gid];
            u32 bl1 = Hslo[(kb2 + tig + 4) * 8 + gid];
            mma_bf16(aH, ahi[kt], bh0, bh1);
            mma_bf16(aM, ahi[kt], bl0, bl1);
            mma_bf16(aL, alo[kt], bh0, bh1);
        }
        float acc[4];
        #pragma unroll
        for (int i = 0; i < 4; i++) acc[i] = aH[i] + aM[i] + aL[i];

        // cross-warp K reduction
        if (kh == 1){
            float* rp = &Red[(m * 32 + lane) * 4];
            rp[0] = acc[0]; rp[1] = acc[1]; rp[2] = acc[2]; rp[3] = acc[3];
        }
        __syncthreads();
        if (kh == 0){
            const float* rp = &Red[(m * 32 + lane) * 4];
            float* gp = &Gt[(m * 16 + gid) * 8 + 2 * tig];
            gp[0]  = acc[0] + rp[0] + xa.x;
            gp[1]  = acc[1] + rp[1] + xa.y;
            gp[64] = acc[2] + rp[2] + xb.x;
            gp[65] = acc[3] + rp[3] + xb.y;
        }
        __syncthreads();

        // activations + state update (128 threads = 16 units x 8 batches)
        if (tid < 128){
            int u = tid >> 3, b = tid & 7, j = j0 + u;
            float gi = sigm (Gt[        u * 8 + b]);
            float gf = sigm (Gt[128 +   u * 8 + b]);
            float gg = tanhf(Gt[256 +   u * 8 + b]);
            float go = sigm (Gt[384 +   u * 8 + b]);
            float c  = gf * Cs[tid] + gi * gg;
            Cs[tid]  = c;
            float h  = go * tanhf(c);
            if (s == TT - 1){
                out[(size_t)(b0g + b) * HID + j]                          = h;
                out[(size_t)NB * HID + (size_t)(b0g + b) * HID + j]       = c;
            } else {
                u32 hi, lo; splitbf(h, hi, lo);
                size_t idx = ((size_t)((s + 1) & 1) * 4 + group) * (HK * 8) + (j >> 1) * 8 + b;
                ((u16*)(g_hhi + idx))[j & 1] = (u16)hi;
                ((u16*)(g_hlo + idx))[j & 1] = (u16)lo;
            }
        }
        __syncthreads();
        if (tid == 0 && s < TT - 1) bar_arrive(&g_bar[group * 32 + ((sub < 16) ? 0 : 8)]);
    }

    // persist cell state for next chunk
    if (s0 + CH < TT && tid < 128){
        int u = tid >> 3, b = tid & 7;
        g_c[(size_t)(b0g + b) * HID + j0 + u] = Cs[tid];
    }
}

// ---------------- launcher: fork-join dual-stream pipeline ----------------
extern "C" void kernel_launch(void* const* d_in, const int* in_sizes, int n_in,
                              void* d_out, int out_size){
    const float* input = (const float*)d_in[0];
    const float* h0    = (const float*)d_in[1];
    const float* c0    = (const float*)d_in[2];
    const float* W_ih  = (const float*)d_in[3];
    const float* W_hh  = (const float*)d_in[4];
    const float* b_ih  = (const float*)d_in[5];
    const float* b_hh  = (const float*)d_in[6];
    float* out = (float*)d_out;

    static cudaStream_t sA = nullptr, sB = nullptr;
    static cudaEvent_t evStart, evW, evG[NCH], evR[NCH], evEnd;
    static bool inited = false;
    if (!inited){
        cudaStreamCreateWithFlags(&sA, cudaStreamNonBlocking);
        cudaStreamCreateWithFlags(&sB, cudaStreamNonBlocking);
        cudaEventCreateWithFlags(&evStart, cudaEventDisableTiming);
        cudaEventCreateWithFlags(&evW,     cudaEventDisableTiming);
        cudaEventCreateWithFlags(&evEnd,   cudaEventDisableTiming);
        for (int c = 0; c < NCH; c++){
            cudaEventCreateWithFlags(&evG[c], cudaEventDisableTiming);
            cudaEventCreateWithFlags(&evR[c], cudaEventDisableTiming);
        }
        cudaFuncSetAttribute(k_gemm1, cudaFuncAttributeMaxDynamicSharedMemorySize, 2 * BUFU * 4);
        inited = true;
    }

    // fork from capture-origin (default) stream
    cudaEventRecord(evStart, 0);
    cudaStreamWaitEvent(sA, evStart, 0);
    cudaStreamWaitEvent(sB, evStart, 0);

    // stream A: init + weight pack (needed by both streams)
    k_init<<<1, 128, 0, sA>>>();
    k_packw<<<1024, 256, 0, sA>>>(W_ih, W_hh);
    cudaEventRecord(evW, sA);
    cudaStreamWaitEvent(sB, evW, 0);

    for (int c = 0; c < NCH; c++){
        // stream B: projection pipeline for chunk c (buffer c&1)
        if (c >= 2) cudaStreamWaitEvent(sB, evR[c - 2], 0);   // buffer reuse
        k_packx<<<dim3(4, CH), 256, 0, sB>>>(input, c * CH, c & 1);
        k_gemm1<<<dim3(16, CH / 2), 256, 2 * BUFU * 4, sB>>>(b_ih, b_hh, c & 1);
        cudaEventRecord(evG[c], sB);

        // stream A: recurrence for chunk c
        cudaStreamWaitEvent(sA, evG[c], 0);
        k_rec<<<128, 256, 0, sA>>>(h0, c0, out, c * CH, c & 1);
        cudaEventRecord(evR[c], sA);
    }

    // join back to origin stream
    cudaEventRecord(evEnd, sA);
    cudaStreamWaitEvent(0, evEnd, 0);
    cudaStreamWaitEvent(0, evG[NCH - 1], 0);
}